// round 12
// baseline (speedup 1.0000x reference)
#include <cuda_runtime.h>
#include <math.h>

// StatisticalFeatureExtractor: (B=64, C=16, T=65536) fp32 -> (B, C, 17) fp32
// 4-CTA cluster per row; each CTA owns a 64KB quarter (L1-resident).
//   pass 1 (HBM): S1,S2,sum|x|,sum sqrt|x|,min,max,zc on the quarter
//   DSMEM exchange of S1 partials -> row mean (mbarrier handshake, no cluster.sync)
//   pass 2 (L1 re-read): centered d2,d3,d4 + mean-crossings
//   rank0 gathers all partials via DSMEM, finalizes, writes the row.

#define TLEN    65536
#define QLEN    16384
#define QCHUNKS (QLEN / 4)      // 4096 float4 per CTA
#define THREADS 512
#define NWARP   (THREADS / 32)
#define NITER   (QCHUNKS / THREADS)  // 8
#define CLUSTER 4
#define EPSV    1e-8

typedef unsigned long long u64;

__device__ __forceinline__ u64 pk2(float x, float y) {
    u64 r; asm("mov.b64 %0, {%1, %2};" : "=l"(r) : "f"(x), "f"(y)); return r;
}
__device__ __forceinline__ void up2(u64 a, float& x, float& y) {
    asm("mov.b64 {%0, %1}, %2;" : "=f"(x), "=f"(y) : "l"(a));
}
__device__ __forceinline__ u64 add2(u64 a, u64 b) {
    u64 r; asm("add.rn.f32x2 %0, %1, %2;" : "=l"(r) : "l"(a), "l"(b)); return r;
}
__device__ __forceinline__ u64 mul2(u64 a, u64 b) {
    u64 r; asm("mul.rn.f32x2 %0, %1, %2;" : "=l"(r) : "l"(a), "l"(b)); return r;
}
__device__ __forceinline__ u64 fma2(u64 a, u64 b, u64 c) {
    u64 r; asm("fma.rn.f32x2 %0, %1, %2, %3;" : "=l"(r) : "l"(a), "l"(b), "l"(c)); return r;
}
__device__ __forceinline__ float sqrt_approx(float v) {
    float r; asm("sqrt.approx.f32 %0, %1;" : "=f"(r) : "f"(v)); return r;
}
__device__ __forceinline__ float hsum2(u64 a) { float x, y; up2(a, x, y); return x + y; }

__device__ __forceinline__ unsigned cluster_rank() {
    unsigned r; asm("mov.u32 %0, %%cluster_ctarank;" : "=r"(r)); return r;
}
__device__ __forceinline__ unsigned smem_u32(const void* p) {
    return (unsigned)__cvta_generic_to_shared(p);
}
__device__ __forceinline__ void mbar_init(unsigned bar, unsigned cnt) {
    asm volatile("mbarrier.init.shared.b64 [%0], %1;" :: "r"(bar), "r"(cnt) : "memory");
}
// remote arrive on CTA `r`'s barrier at same smem offset (release, cluster scope)
__device__ __forceinline__ void mbar_arrive_rank(unsigned bar, unsigned r) {
    asm volatile(
        "{\n\t.reg .b32 ra;\n\t"
        "mapa.shared::cluster.u32 ra, %0, %1;\n\t"
        "mbarrier.arrive.release.cluster.shared::cluster.b64 _, [ra];\n\t}"
        :: "r"(bar), "r"(r) : "memory");
}
__device__ __forceinline__ void mbar_wait(unsigned bar, unsigned parity) {
    unsigned done;
    do {
        asm volatile(
            "{\n\t.reg .pred p;\n\t"
            "mbarrier.try_wait.parity.acquire.cluster.shared::cta.b64 p, [%1], %2, 0x989680;\n\t"
            "selp.b32 %0, 1, 0, p;\n\t}"
            : "=r"(done) : "r"(bar), "r"(parity) : "memory");
    } while (!done);
}
__device__ __forceinline__ float dsmem_ld_f32(unsigned saddr, unsigned r) {
    float v;
    asm volatile(
        "{\n\t.reg .b32 ra;\n\t"
        "mapa.shared::cluster.u32 ra, %1, %2;\n\t"
        "ld.shared::cluster.f32 %0, [ra];\n\t}"
        : "=f"(v) : "r"(saddr), "r"(r));
    return v;
}
__device__ __forceinline__ int dsmem_ld_s32(unsigned saddr, unsigned r) {
    int v;
    asm volatile(
        "{\n\t.reg .b32 ra;\n\t"
        "mapa.shared::cluster.u32 ra, %1, %2;\n\t"
        "ld.shared::cluster.s32 %0, [ra];\n\t}"
        : "=r"(v) : "r"(saddr), "r"(r));
    return v;
}

__device__ __forceinline__ float warp_sum(float v) {
#pragma unroll
    for (int o = 16; o; o >>= 1) v += __shfl_xor_sync(0xffffffffu, v, o);
    return v;
}
__device__ __forceinline__ int warp_sumi(int v) {
#pragma unroll
    for (int o = 16; o; o >>= 1) v += __shfl_xor_sync(0xffffffffu, v, o);
    return v;
}
__device__ __forceinline__ float warp_max(float v) {
#pragma unroll
    for (int o = 16; o; o >>= 1) v = fmaxf(v, __shfl_xor_sync(0xffffffffu, v, o));
    return v;
}
__device__ __forceinline__ float warp_min(float v) {
#pragma unroll
    for (int o = 16; o; o >>= 1) v = fminf(v, __shfl_xor_sync(0xffffffffu, v, o));
    return v;
}

__global__ __launch_bounds__(THREADS, 2) __cluster_dims__(CLUSTER, 1, 1)
void stat_feat_kernel(const float* __restrict__ x, float* __restrict__ out) {
    const int row = blockIdx.x >> 2;
    const unsigned rank = cluster_rank();
    const float* __restrict__ xq = x + (size_t)row * TLEN + (size_t)rank * QLEN;
    const float4* __restrict__ x4 = reinterpret_cast<const float4*>(xq);

    const int tid  = threadIdx.x;
    const int wid  = tid >> 5;
    const int lane = tid & 31;
    const unsigned vmask = (lane != 31) ? 1u : 0u;

    __shared__ float w_a[NWARP], w_b[NWARP], w_c[NWARP], w_d[NWARP];
    __shared__ float w_mx[NWARP], w_mn[NWARP];
    __shared__ int   w_i[NWARP], w_j[NWARP];
    __shared__ float s_mean;
    // DSMEM-published partials
    __shared__ float ex1[6];   // S1,S2,Sa,Sq,mx,mn
    __shared__ int   exi1;     // zc
    __shared__ float ex2[3];   // D2,D3,D4
    __shared__ int   exi2[2];  // mc, zce
    __shared__ __align__(8) u64 bars[3];  // bar_a(mean), bar_b(final), bar_c(done)

    const unsigned bar_a = smem_u32(&bars[0]);
    const unsigned bar_b = smem_u32(&bars[1]);
    const unsigned bar_c = smem_u32(&bars[2]);
    const unsigned a_ex1 = smem_u32(ex1);
    const unsigned a_exi1 = smem_u32(&exi1);
    const unsigned a_ex2 = smem_u32(ex2);
    const unsigned a_exi2 = smem_u32(exi2);

    if (tid == 0) {
        mbar_init(bar_a, CLUSTER);
        mbar_init(bar_b, CLUSTER);
        mbar_init(bar_c, CLUSTER);
    }
    __syncthreads();
    // one rendezvous so all mbarrier inits are visible before any remote arrive.
    // (pre-pass-1, so any L1 flush here is harmless)
    asm volatile("barrier.cluster.arrive.aligned;" ::: "memory");
    asm volatile("barrier.cluster.wait.aligned;" ::: "memory");

    const u64 ABSM = 0x7fffffff7fffffffULL;

    // ================= pass 1: raw sums on the quarter (HBM) =================
    u64 s1p = 0, s2p = 0, sap = 0;
    float sq = 0.f;
    float mx = -INFINITY, mn = INFINITY;
    int zc = 0;

#pragma unroll
    for (int i = 0; i < NITER; i++) {
        float4 v = x4[tid + i * THREADS];
        u64 plo = pk2(v.x, v.y), phi = pk2(v.z, v.w);
        s1p = add2(s1p, add2(plo, phi));
        s2p = fma2(plo, plo, s2p);
        s2p = fma2(phi, phi, s2p);

        u64 alo = plo & ABSM, ahi = phi & ABSM;
        sap = add2(sap, add2(alo, ahi));

        float b0, b1, b2, b3;
        up2(alo, b0, b1); up2(ahi, b2, b3);
        sq += (sqrt_approx(b0) + sqrt_approx(b1)) + (sqrt_approx(b2) + sqrt_approx(b3));

        mx = fmaxf(mx, fmaxf(fmaxf(v.x, v.y), fmaxf(v.z, v.w)));
        mn = fminf(mn, fminf(fminf(v.x, v.y), fminf(v.z, v.w)));

        unsigned u0 = __float_as_uint(v.x), u1 = __float_as_uint(v.y);
        unsigned u2 = __float_as_uint(v.z), u3 = __float_as_uint(v.w);
        unsigned nu0 = __shfl_down_sync(0xffffffffu, u0, 1);
        zc += (int)(((u0 ^ u1) >> 31) + ((u1 ^ u2) >> 31) + ((u2 ^ u3) >> 31)
                    + (((u3 ^ nu0) >> 31) & vmask));
    }

    {
        float s1 = hsum2(s1p), s2 = hsum2(s2p), sa = hsum2(sap);
        s1 = warp_sum(s1); s2 = warp_sum(s2); sa = warp_sum(sa); sq = warp_sum(sq);
        mx = warp_max(mx); mn = warp_min(mn); zc = warp_sumi(zc);
        if (lane == 0) {
            w_a[wid] = s1; w_b[wid] = s2; w_c[wid] = sa; w_d[wid] = sq;
            w_mx[wid] = mx; w_mn[wid] = mn; w_i[wid] = zc;
        }
    }
    __syncthreads();
    if (tid == 0) {
        float S1 = 0, S2 = 0, Sa = 0, Sq = 0;
        float rmx = -INFINITY, rmn = INFINITY;
        int rzc = 0;
        for (int i = 0; i < NWARP; i++) {
            S1 += w_a[i]; S2 += w_b[i]; Sa += w_c[i]; Sq += w_d[i];
            rmx = fmaxf(rmx, w_mx[i]); rmn = fminf(rmn, w_mn[i]);
            rzc += w_i[i];
        }
        ex1[0] = S1; ex1[1] = S2; ex1[2] = Sa; ex1[3] = Sq;
        ex1[4] = rmx; ex1[5] = rmn; exi1 = rzc;
        // publish partials to all 4 CTAs (release-arrive)
        for (unsigned r = 0; r < CLUSTER; r++) mbar_arrive_rank(bar_a, r);
        // row mean = sum of the 4 quarter S1s
        mbar_wait(bar_a, 0);
        double S1t = 0.0;
        for (unsigned r = 0; r < CLUSTER; r++) S1t += (double)dsmem_ld_f32(a_ex1 + 0, r);
        s_mean = (float)(S1t * (1.0 / (double)TLEN));
    }
    __syncthreads();

    const float mean = s_mean;
    const u64 nm2 = pk2(-mean, -mean);

    // ================= pass 2: centered moments + mean crossings (L1) =================
    u64 d2p = 0, d3p = 0, d4p = 0;
    int mc = 0;

#pragma unroll
    for (int i = 0; i < NITER; i++) {
        float4 v = x4[tid + i * THREADS];
        u64 dlo = add2(pk2(v.x, v.y), nm2), dhi = add2(pk2(v.z, v.w), nm2);
        u64 tlo = mul2(dlo, dlo), thi = mul2(dhi, dhi);

        d2p = add2(d2p, add2(tlo, thi));
        d3p = fma2(tlo, dlo, d3p);
        d3p = fma2(thi, dhi, d3p);
        d4p = fma2(tlo, tlo, d4p);
        d4p = fma2(thi, thi, d4p);

        float d0, d1, d2v, d3v;
        up2(dlo, d0, d1); up2(dhi, d2v, d3v);
        unsigned u0 = __float_as_uint(d0), u1 = __float_as_uint(d1);
        unsigned u2 = __float_as_uint(d2v), u3 = __float_as_uint(d3v);
        unsigned nu0 = __shfl_down_sync(0xffffffffu, u0, 1);
        mc += (int)(((u0 ^ u1) >> 31) + ((u1 ^ u2) >> 31) + ((u2 ^ u3) >> 31)
                    + (((u3 ^ nu0) >> 31) & vmask));
    }

    // ---- cleanup: this quarter's 128 warp-span boundary pairs (zcr & mcr) ----
    // local pair (128t+127, 128t+128); last pair of rank 3 is the row end -> skip.
    int zce = 0;
    if (tid < 128) {
        int gidx = (int)rank * QLEN + 128 * tid + 128;   // absolute successor index
        if (gidx < TLEN) {
            float a = __ldg(xq + 128 * tid + 127);
            float b = __ldg(xq + 128 * tid + 128);
            zce = (int)((__float_as_uint(a) ^ __float_as_uint(b)) >> 31);
            float ca = a - mean, cb = b - mean;
            mc += (int)((__float_as_uint(ca) ^ __float_as_uint(cb)) >> 31);
        }
    }

    float d2 = hsum2(d2p), d3 = hsum2(d3p), d4 = hsum2(d4p);
    d2 = warp_sum(d2); d3 = warp_sum(d3); d4 = warp_sum(d4);
    mc = warp_sumi(mc); zce = warp_sumi(zce);
    if (lane == 0) { w_a[wid] = d2; w_b[wid] = d3; w_c[wid] = d4; w_i[wid] = mc; w_j[wid] = zce; }
    __syncthreads();

    if (tid == 0) {
        float D2 = 0, D3 = 0, D4 = 0;
        int rmc = 0, rzce = 0;
        for (int i = 0; i < NWARP; i++) {
            D2 += w_a[i]; D3 += w_b[i]; D4 += w_c[i];
            rmc += w_i[i]; rzce += w_j[i];
        }
        ex2[0] = D2; ex2[1] = D3; ex2[2] = D4;
        exi2[0] = rmc; exi2[1] = rzce;
        for (unsigned r = 0; r < CLUSTER; r++) mbar_arrive_rank(bar_b, r);

        if (rank == 0) {
            mbar_wait(bar_b, 0);
            double S1 = 0, S2 = 0, Sa = 0, Sq = 0, D2t = 0, D3t = 0, D4t = 0;
            float pk = -INFINITY, pkn = INFINITY;
            int zct = 0, mct = 0;
            for (unsigned r = 0; r < CLUSTER; r++) {
                S1 += (double)dsmem_ld_f32(a_ex1 + 0,  r);
                S2 += (double)dsmem_ld_f32(a_ex1 + 4,  r);
                Sa += (double)dsmem_ld_f32(a_ex1 + 8,  r);
                Sq += (double)dsmem_ld_f32(a_ex1 + 12, r);
                pk  = fmaxf(pk,  dsmem_ld_f32(a_ex1 + 16, r));
                pkn = fminf(pkn, dsmem_ld_f32(a_ex1 + 20, r));
                zct += dsmem_ld_s32(a_exi1, r);
                D2t += (double)dsmem_ld_f32(a_ex2 + 0, r);
                D3t += (double)dsmem_ld_f32(a_ex2 + 4, r);
                D4t += (double)dsmem_ld_f32(a_ex2 + 8, r);
                mct += dsmem_ld_s32(a_exi2 + 0, r);
                zct += dsmem_ld_s32(a_exi2 + 4, r);
            }

            const double Td   = (double)TLEN;
            const double invT = 1.0 / Td;
            double meanv     = S1 * invT;
            double var       = D2t / (Td - 1.0);
            double stdv      = sqrt(var);
            double sq_mean   = S2 * invT;
            double rms       = sqrt(sq_mean);
            double ptp       = (double)pk - (double)pkn;
            double abs_peak  = fabs((double)pk);
            double crest     = abs_peak / (rms + EPSV);
            double mean_abs  = Sa * invT;
            double shape     = rms / (mean_abs + EPSV);
            double impulse   = abs_peak / (mean_abs + EPSV);
            double sqrt_mean = Sq * invT;
            double clearance = abs_peak / (sqrt_mean * sqrt_mean + EPSV);
            double skew      = (D3t * invT) / (stdv * stdv * stdv + EPSV);
            double kurt      = (D4t * invT) / (var * var + EPSV) - 3.0;
            double zcr       = (double)zct / (Td - 1.0);
            double mcr       = (double)mct / (Td - 1.0);
            double margin    = abs_peak / (sqrt_mean + EPSV);
            double energy    = S2;

            float* o = out + (size_t)row * 17;
            o[0]  = (float)meanv;
            o[1]  = (float)stdv;
            o[2]  = (float)var;
            o[3]  = (float)rms;
            o[4]  = (float)pk;
            o[5]  = (float)pkn;
            o[6]  = (float)ptp;
            o[7]  = (float)crest;
            o[8]  = (float)shape;
            o[9]  = (float)impulse;
            o[10] = (float)clearance;
            o[11] = (float)skew;
            o[12] = (float)kurt;
            o[13] = (float)zcr;
            o[14] = (float)mcr;
            o[15] = (float)margin;
            o[16] = (float)energy;
        }
        // done handshake: no CTA exits while peers may still read its smem
        for (unsigned r = 0; r < CLUSTER; r++) mbar_arrive_rank(bar_c, r);
        mbar_wait(bar_c, 0);
    }
}

extern "C" void kernel_launch(void* const* d_in, const int* in_sizes, int n_in,
                              void* d_out, int out_size) {
    const float* x = (const float*)d_in[0];
    float* out = (float*)d_out;
    int rows = in_sizes[0] / TLEN;         // 1024
    stat_feat_kernel<<<rows * CLUSTER, THREADS>>>(x, out);
}

// round 13
// speedup vs baseline: 1.3603x; 1.3603x over previous
#include <cuda_runtime.h>
#include <math.h>

// StatisticalFeatureExtractor: (B=64, C=16, T=65536) fp32 -> (B, C, 17) fp32
// One CTA (512 thr) per row, 1 CTA/SM, 192KB SMEM stash.
//   pass 1 (HBM): S1,S2,sum|x|,sum sqrt|x|,min,max,zc; stash first 24/32 of row in SMEM
//   pass 2: centered d2,d3,d4 + mean-crossings; 24/32 from SMEM, 8/32 from L2
// Branch-free sign logic; warp-span boundary pairs in one cleanup step.

#define TLEN    65536
#define CHUNKS  (TLEN / 4)       // 16384 float4
#define THREADS 512
#define NWARP   (THREADS / 32)
#define NITER   (CHUNKS / THREADS)   // 32
#define SITER   24                   // stages stashed in SMEM (24*8KB = 192KB)
#define SMEM_BYTES (SITER * THREADS * 16)
#define EPSV    1e-8

typedef unsigned long long u64;

__device__ __forceinline__ u64 pk2(float x, float y) {
    u64 r; asm("mov.b64 %0, {%1, %2};" : "=l"(r) : "f"(x), "f"(y)); return r;
}
__device__ __forceinline__ void up2(u64 a, float& x, float& y) {
    asm("mov.b64 {%0, %1}, %2;" : "=f"(x), "=f"(y) : "l"(a));
}
__device__ __forceinline__ u64 add2(u64 a, u64 b) {
    u64 r; asm("add.rn.f32x2 %0, %1, %2;" : "=l"(r) : "l"(a), "l"(b)); return r;
}
__device__ __forceinline__ u64 mul2(u64 a, u64 b) {
    u64 r; asm("mul.rn.f32x2 %0, %1, %2;" : "=l"(r) : "l"(a), "l"(b)); return r;
}
__device__ __forceinline__ u64 fma2(u64 a, u64 b, u64 c) {
    u64 r; asm("fma.rn.f32x2 %0, %1, %2, %3;" : "=l"(r) : "l"(a), "l"(b), "l"(c)); return r;
}
__device__ __forceinline__ float sqrt_approx(float v) {
    float r; asm("sqrt.approx.f32 %0, %1;" : "=f"(r) : "f"(v)); return r;
}
__device__ __forceinline__ float hsum2(u64 a) { float x, y; up2(a, x, y); return x + y; }

__device__ __forceinline__ float warp_sum(float v) {
#pragma unroll
    for (int o = 16; o; o >>= 1) v += __shfl_xor_sync(0xffffffffu, v, o);
    return v;
}
__device__ __forceinline__ int warp_sumi(int v) {
#pragma unroll
    for (int o = 16; o; o >>= 1) v += __shfl_xor_sync(0xffffffffu, v, o);
    return v;
}
__device__ __forceinline__ float warp_max(float v) {
#pragma unroll
    for (int o = 16; o; o >>= 1) v = fmaxf(v, __shfl_xor_sync(0xffffffffu, v, o));
    return v;
}
__device__ __forceinline__ float warp_min(float v) {
#pragma unroll
    for (int o = 16; o; o >>= 1) v = fminf(v, __shfl_xor_sync(0xffffffffu, v, o));
    return v;
}

__global__ __launch_bounds__(THREADS, 1)
void stat_feat_kernel(const float* __restrict__ x, float* __restrict__ out) {
    extern __shared__ float4 stash[];   // [SITER][THREADS], thread-private slots

    const int row = blockIdx.x;
    const float* __restrict__ xr = x + (size_t)row * TLEN;
    const float4* __restrict__ x4 = reinterpret_cast<const float4*>(xr);

    const int tid  = threadIdx.x;
    const int wid  = tid >> 5;
    const int lane = tid & 31;
    const unsigned vmask = (lane != 31) ? 1u : 0u;

    __shared__ float w_a[NWARP], w_b[NWARP], w_c[NWARP], w_d[NWARP];
    __shared__ float w_mx[NWARP], w_mn[NWARP];
    __shared__ int   w_i[NWARP], w_j[NWARP];
    __shared__ float s_mean;
    __shared__ float s_res[6];
    __shared__ int   s_zc;

    const u64 ABSM = 0x7fffffff7fffffffULL;

    // ================= pass 1: raw sums (HBM stream) + SMEM stash =================
    u64 s1p = 0, s2p = 0, sap = 0;
    float sq = 0.f;
    float mx = -INFINITY, mn = INFINITY;
    int zc = 0;

#pragma unroll 8
    for (int i = 0; i < NITER; i++) {
        float4 v = x4[i * THREADS + tid];
        if (i < SITER) stash[i * THREADS + tid] = v;

        u64 plo = pk2(v.x, v.y), phi = pk2(v.z, v.w);
        s1p = add2(s1p, add2(plo, phi));
        s2p = fma2(plo, plo, s2p);
        s2p = fma2(phi, phi, s2p);

        u64 alo = plo & ABSM, ahi = phi & ABSM;
        sap = add2(sap, add2(alo, ahi));

        float b0, b1, b2, b3;
        up2(alo, b0, b1); up2(ahi, b2, b3);
        sq += (sqrt_approx(b0) + sqrt_approx(b1)) + (sqrt_approx(b2) + sqrt_approx(b3));

        mx = fmaxf(mx, fmaxf(fmaxf(v.x, v.y), fmaxf(v.z, v.w)));
        mn = fminf(mn, fminf(fminf(v.x, v.y), fminf(v.z, v.w)));

        unsigned u0 = __float_as_uint(v.x), u1 = __float_as_uint(v.y);
        unsigned u2 = __float_as_uint(v.z), u3 = __float_as_uint(v.w);
        unsigned nu0 = __shfl_down_sync(0xffffffffu, u0, 1);
        zc += (int)(((u0 ^ u1) >> 31) + ((u1 ^ u2) >> 31) + ((u2 ^ u3) >> 31)
                    + (((u3 ^ nu0) >> 31) & vmask));
    }

    {
        float s1 = hsum2(s1p), s2 = hsum2(s2p), sa = hsum2(sap);
        s1 = warp_sum(s1); s2 = warp_sum(s2); sa = warp_sum(sa); sq = warp_sum(sq);
        mx = warp_max(mx); mn = warp_min(mn); zc = warp_sumi(zc);
        if (lane == 0) {
            w_a[wid] = s1; w_b[wid] = s2; w_c[wid] = sa; w_d[wid] = sq;
            w_mx[wid] = mx; w_mn[wid] = mn; w_i[wid] = zc;
        }
    }
    __syncthreads();
    if (tid == 0) {
        double S1 = 0, S2 = 0, Sa = 0, Sq = 0;
        float rmx = -INFINITY, rmn = INFINITY;
        int rzc = 0;
        for (int i = 0; i < NWARP; i++) {
            S1 += (double)w_a[i]; S2 += (double)w_b[i];
            Sa += (double)w_c[i]; Sq += (double)w_d[i];
            rmx = fmaxf(rmx, w_mx[i]); rmn = fminf(rmn, w_mn[i]);
            rzc += w_i[i];
        }
        s_res[0] = (float)S1; s_res[1] = (float)S2;
        s_res[2] = (float)Sa; s_res[3] = (float)Sq;
        s_res[4] = rmx; s_res[5] = rmn;
        s_zc = rzc;
        s_mean = (float)(S1 * (1.0 / (double)TLEN));
    }
    __syncthreads();

    const float mean = s_mean;
    const u64 nm2 = pk2(-mean, -mean);

    // ================= pass 2: centered moments + mean crossings =================
    u64 d2p = 0, d3p = 0, d4p = 0;
    int mc = 0;

    // 2a: SMEM-resident portion (thread reads only its own stashed slots)
#pragma unroll 8
    for (int i = 0; i < SITER; i++) {
        float4 v = stash[i * THREADS + tid];
        u64 dlo = add2(pk2(v.x, v.y), nm2), dhi = add2(pk2(v.z, v.w), nm2);
        u64 tlo = mul2(dlo, dlo), thi = mul2(dhi, dhi);

        d2p = add2(d2p, add2(tlo, thi));
        d3p = fma2(tlo, dlo, d3p);
        d3p = fma2(thi, dhi, d3p);
        d4p = fma2(tlo, tlo, d4p);
        d4p = fma2(thi, thi, d4p);

        float d0, d1, d2v, d3v;
        up2(dlo, d0, d1); up2(dhi, d2v, d3v);
        unsigned u0 = __float_as_uint(d0), u1 = __float_as_uint(d1);
        unsigned u2 = __float_as_uint(d2v), u3 = __float_as_uint(d3v);
        unsigned nu0 = __shfl_down_sync(0xffffffffu, u0, 1);
        mc += (int)(((u0 ^ u1) >> 31) + ((u1 ^ u2) >> 31) + ((u2 ^ u3) >> 31)
                    + (((u3 ^ nu0) >> 31) & vmask));
    }

    // 2b: L2-resident tail (last 8 stages, recently streamed)
#pragma unroll 8
    for (int i = SITER; i < NITER; i++) {
        float4 v = x4[i * THREADS + tid];
        u64 dlo = add2(pk2(v.x, v.y), nm2), dhi = add2(pk2(v.z, v.w), nm2);
        u64 tlo = mul2(dlo, dlo), thi = mul2(dhi, dhi);

        d2p = add2(d2p, add2(tlo, thi));
        d3p = fma2(tlo, dlo, d3p);
        d3p = fma2(thi, dhi, d3p);
        d4p = fma2(tlo, tlo, d4p);
        d4p = fma2(thi, thi, d4p);

        float d0, d1, d2v, d3v;
        up2(dlo, d0, d1); up2(dhi, d2v, d3v);
        unsigned u0 = __float_as_uint(d0), u1 = __float_as_uint(d1);
        unsigned u2 = __float_as_uint(d2v), u3 = __float_as_uint(d3v);
        unsigned nu0 = __shfl_down_sync(0xffffffffu, u0, 1);
        mc += (int)(((u0 ^ u1) >> 31) + ((u1 ^ u2) >> 31) + ((u2 ^ u3) >> 31)
                    + (((u3 ^ nu0) >> 31) & vmask));
    }

    // ---------- cleanup: 511 warp-span boundary pairs (zcr & mcr), L2 hits ----------
    int zce = 0;
    if (tid < 511) {
        float a = __ldg(xr + 128 * tid + 127);
        float b = __ldg(xr + 128 * tid + 128);
        zce = (int)((__float_as_uint(a) ^ __float_as_uint(b)) >> 31);
        float ca = a - mean, cb = b - mean;
        mc += (int)((__float_as_uint(ca) ^ __float_as_uint(cb)) >> 31);
    }

    float d2 = hsum2(d2p), d3 = hsum2(d3p), d4 = hsum2(d4p);
    d2 = warp_sum(d2); d3 = warp_sum(d3); d4 = warp_sum(d4);
    mc = warp_sumi(mc); zce = warp_sumi(zce);
    if (lane == 0) { w_a[wid] = d2; w_b[wid] = d3; w_c[wid] = d4; w_i[wid] = mc; w_j[wid] = zce; }
    __syncthreads();

    if (tid == 0) {
        double D2 = 0.0, D3 = 0.0, D4 = 0.0;
        int rmc = 0, rzce = 0;
        for (int i = 0; i < NWARP; i++) {
            D2 += (double)w_a[i]; D3 += (double)w_b[i]; D4 += (double)w_c[i];
            rmc += w_i[i]; rzce += w_j[i];
        }

        const double Td   = (double)TLEN;
        const double invT = 1.0 / Td;
        double S1 = s_res[0], S2 = s_res[1], Sa = s_res[2], Sq = s_res[3];
        double pk = s_res[4], pkn = s_res[5];
        int    zct = s_zc + rzce;

        double meanv     = S1 * invT;
        double var       = D2 / (Td - 1.0);
        double stdv      = sqrt(var);
        double sq_mean   = S2 * invT;
        double rms       = sqrt(sq_mean);
        double ptp       = pk - pkn;
        double abs_peak  = fabs(pk);
        double crest     = abs_peak / (rms + EPSV);
        double mean_abs  = Sa * invT;
        double shape     = rms / (mean_abs + EPSV);
        double impulse   = abs_peak / (mean_abs + EPSV);
        double sqrt_mean = Sq * invT;
        double clearance = abs_peak / (sqrt_mean * sqrt_mean + EPSV);
        double skew      = (D3 * invT) / (stdv * stdv * stdv + EPSV);
        double kurt      = (D4 * invT) / (var * var + EPSV) - 3.0;
        double zcr       = (double)zct / (Td - 1.0);
        double mcr       = (double)rmc / (Td - 1.0);
        double margin    = abs_peak / (sqrt_mean + EPSV);
        double energy    = S2;

        float* o = out + (size_t)row * 17;
        o[0]  = (float)meanv;
        o[1]  = (float)stdv;
        o[2]  = (float)var;
        o[3]  = (float)rms;
        o[4]  = (float)pk;
        o[5]  = (float)pkn;
        o[6]  = (float)ptp;
        o[7]  = (float)crest;
        o[8]  = (float)shape;
        o[9]  = (float)impulse;
        o[10] = (float)clearance;
        o[11] = (float)skew;
        o[12] = (float)kurt;
        o[13] = (float)zcr;
        o[14] = (float)mcr;
        o[15] = (float)margin;
        o[16] = (float)energy;
    }
}

extern "C" void kernel_launch(void* const* d_in, const int* in_sizes, int n_in,
                              void* d_out, int out_size) {
    const float* x = (const float*)d_in[0];
    float* out = (float*)d_out;
    int rows = in_sizes[0] / TLEN;   // 1024
    cudaFuncSetAttribute(stat_feat_kernel,
                         cudaFuncAttributeMaxDynamicSharedMemorySize, SMEM_BYTES);
    stat_feat_kernel<<<rows, THREADS, SMEM_BYTES>>>(x, out);
}

// round 15
// speedup vs baseline: 2.0429x; 1.5018x over previous
#include <cuda_runtime.h>
#include <math.h>

// StatisticalFeatureExtractor: (B=64, C=16, T=65536) fp32 -> (B, C, 17) fp32
// One CTA (512 thr) per row, 2 CTAs/SM. Two passes (pass 2 L2-resident):
//   pass 1 (DRAM, minimal): S1, min, max, zero-crossings
//   pass 2 (L2, heavy): Sa, Sq(MUFU), centered d2,d3,d4, mean-crossings
// S2 reconstructed exactly from D2 + mean in double. Branch-free sign logic;
// warp-span boundary pairs in one cleanup step. unroll 8 for MLP.

#define TLEN    65536
#define CHUNKS  (TLEN / 4)
#define THREADS 512
#define NWARP   (THREADS / 32)
#define EPSV    1e-8

typedef unsigned long long u64;

__device__ __forceinline__ u64 pk2(float x, float y) {
    u64 r; asm("mov.b64 %0, {%1, %2};" : "=l"(r) : "f"(x), "f"(y)); return r;
}
__device__ __forceinline__ void up2(u64 a, float& x, float& y) {
    asm("mov.b64 {%0, %1}, %2;" : "=f"(x), "=f"(y) : "l"(a));
}
__device__ __forceinline__ u64 add2(u64 a, u64 b) {
    u64 r; asm("add.rn.f32x2 %0, %1, %2;" : "=l"(r) : "l"(a), "l"(b)); return r;
}
__device__ __forceinline__ u64 mul2(u64 a, u64 b) {
    u64 r; asm("mul.rn.f32x2 %0, %1, %2;" : "=l"(r) : "l"(a), "l"(b)); return r;
}
__device__ __forceinline__ u64 fma2(u64 a, u64 b, u64 c) {
    u64 r; asm("fma.rn.f32x2 %0, %1, %2, %3;" : "=l"(r) : "l"(a), "l"(b), "l"(c)); return r;
}
__device__ __forceinline__ float sqrt_approx(float v) {
    float r; asm("sqrt.approx.f32 %0, %1;" : "=f"(r) : "f"(v)); return r;
}
__device__ __forceinline__ float hsum2(u64 a) { float x, y; up2(a, x, y); return x + y; }

__device__ __forceinline__ float warp_sum(float v) {
#pragma unroll
    for (int o = 16; o; o >>= 1) v += __shfl_xor_sync(0xffffffffu, v, o);
    return v;
}
__device__ __forceinline__ int warp_sumi(int v) {
#pragma unroll
    for (int o = 16; o; o >>= 1) v += __shfl_xor_sync(0xffffffffu, v, o);
    return v;
}
__device__ __forceinline__ float warp_max(float v) {
#pragma unroll
    for (int o = 16; o; o >>= 1) v = fmaxf(v, __shfl_xor_sync(0xffffffffu, v, o));
    return v;
}
__device__ __forceinline__ float warp_min(float v) {
#pragma unroll
    for (int o = 16; o; o >>= 1) v = fminf(v, __shfl_xor_sync(0xffffffffu, v, o));
    return v;
}

__global__ __launch_bounds__(THREADS, 2)
void stat_feat_kernel(const float* __restrict__ x, float* __restrict__ out) {
    const int row = blockIdx.x;
    const float* __restrict__ xr = x + (size_t)row * TLEN;
    const float4* __restrict__ x4 = reinterpret_cast<const float4*>(xr);

    const int tid  = threadIdx.x;
    const int wid  = tid >> 5;
    const int lane = tid & 31;
    const unsigned vmask = (lane != 31) ? 1u : 0u;

    __shared__ float w_a[NWARP], w_b[NWARP], w_c[NWARP], w_d[NWARP], w_e[NWARP];
    __shared__ float w_mx[NWARP], w_mn[NWARP];
    __shared__ int   w_i[NWARP], w_j[NWARP];
    __shared__ double s_S1;
    __shared__ float  s_mean, s_pk, s_pkn;
    __shared__ int    s_zc;

    const u64 ABSM = 0x7fffffff7fffffffULL;

    // ================= pass 1: minimal raw scan (DRAM stream) =================
    // Only what's needed before the mean exists: S1, min, max, zero-crossings.
    u64 s1p = 0;
    float mx = -INFINITY, mn = INFINITY;
    int zc = 0;

#pragma unroll 8
    for (int k = tid; k < CHUNKS; k += THREADS) {
        float4 v = x4[k];
        u64 plo = pk2(v.x, v.y), phi = pk2(v.z, v.w);
        s1p = add2(s1p, add2(plo, phi));

        mx = fmaxf(mx, fmaxf(fmaxf(v.x, v.y), fmaxf(v.z, v.w)));
        mn = fminf(mn, fminf(fminf(v.x, v.y), fminf(v.z, v.w)));

        unsigned u0 = __float_as_uint(v.x), u1 = __float_as_uint(v.y);
        unsigned u2 = __float_as_uint(v.z), u3 = __float_as_uint(v.w);
        unsigned nu0 = __shfl_down_sync(0xffffffffu, u0, 1);
        zc += (int)(((u0 ^ u1) >> 31) + ((u1 ^ u2) >> 31) + ((u2 ^ u3) >> 31)
                    + (((u3 ^ nu0) >> 31) & vmask));
    }

    {
        float s1 = hsum2(s1p);
        s1 = warp_sum(s1);
        mx = warp_max(mx); mn = warp_min(mn); zc = warp_sumi(zc);
        if (lane == 0) { w_a[wid] = s1; w_mx[wid] = mx; w_mn[wid] = mn; w_i[wid] = zc; }
    }
    __syncthreads();
    if (tid == 0) {
        double S1 = 0.0;
        float rmx = -INFINITY, rmn = INFINITY;
        int rzc = 0;
        for (int i = 0; i < NWARP; i++) {
            S1 += (double)w_a[i];
            rmx = fmaxf(rmx, w_mx[i]); rmn = fminf(rmn, w_mn[i]);
            rzc += w_i[i];
        }
        s_S1 = S1; s_pk = rmx; s_pkn = rmn; s_zc = rzc;
        s_mean = (float)(S1 * (1.0 / (double)TLEN));
    }
    __syncthreads();

    const float mean = s_mean;
    const u64 nm2 = pk2(-mean, -mean);

    // ================= pass 2: heavy stats (L2 re-read) =================
    u64 d2p = 0, d3p = 0, d4p = 0, sap = 0;
    float sq0 = 0.f, sq1 = 0.f;
    int mc = 0;

#pragma unroll 8
    for (int k = tid; k < CHUNKS; k += THREADS) {
        float4 v = x4[k];
        u64 plo = pk2(v.x, v.y), phi = pk2(v.z, v.w);

        // abs sums + sqrt-of-abs (MUFU)
        u64 alo = plo & ABSM, ahi = phi & ABSM;
        sap = add2(sap, add2(alo, ahi));
        float b0, b1, b2, b3;
        up2(alo, b0, b1); up2(ahi, b2, b3);
        sq0 += sqrt_approx(b0) + sqrt_approx(b1);
        sq1 += sqrt_approx(b2) + sqrt_approx(b3);

        // centered moments
        u64 dlo = add2(plo, nm2), dhi = add2(phi, nm2);
        u64 tlo = mul2(dlo, dlo), thi = mul2(dhi, dhi);
        d2p = add2(d2p, add2(tlo, thi));
        d3p = fma2(tlo, dlo, d3p);
        d3p = fma2(thi, dhi, d3p);
        d4p = fma2(tlo, tlo, d4p);
        d4p = fma2(thi, thi, d4p);

        // mean crossings
        float d0, d1, d2v, d3v;
        up2(dlo, d0, d1); up2(dhi, d2v, d3v);
        unsigned u0 = __float_as_uint(d0), u1 = __float_as_uint(d1);
        unsigned u2 = __float_as_uint(d2v), u3 = __float_as_uint(d3v);
        unsigned nu0 = __shfl_down_sync(0xffffffffu, u0, 1);
        mc += (int)(((u0 ^ u1) >> 31) + ((u1 ^ u2) >> 31) + ((u2 ^ u3) >> 31)
                    + (((u3 ^ nu0) >> 31) & vmask));
    }

    // ---------- cleanup: 511 warp-span boundary pairs (zcr & mcr), L2 hits ----------
    int zce = 0;
    if (tid < 511) {
        float a = __ldg(xr + 128 * tid + 127);
        float b = __ldg(xr + 128 * tid + 128);
        zce = (int)((__float_as_uint(a) ^ __float_as_uint(b)) >> 31);
        float ca = a - mean, cb = b - mean;
        mc += (int)((__float_as_uint(ca) ^ __float_as_uint(cb)) >> 31);
    }

    {
        float d2 = hsum2(d2p), d3 = hsum2(d3p), d4 = hsum2(d4p);
        float sa = hsum2(sap), sqv = sq0 + sq1;
        d2 = warp_sum(d2); d3 = warp_sum(d3); d4 = warp_sum(d4);
        sa = warp_sum(sa); sqv = warp_sum(sqv);
        mc = warp_sumi(mc); zce = warp_sumi(zce);
        if (lane == 0) {
            w_a[wid] = d2; w_b[wid] = d3; w_c[wid] = d4;
            w_d[wid] = sa; w_e[wid] = sqv;
            w_i[wid] = mc; w_j[wid] = zce;
        }
    }
    __syncthreads();

    if (tid == 0) {
        double D2 = 0.0, D3 = 0.0, D4 = 0.0, Sa = 0.0, Sq = 0.0;
        int rmc = 0, rzce = 0;
        for (int i = 0; i < NWARP; i++) {
            D2 += (double)w_a[i]; D3 += (double)w_b[i]; D4 += (double)w_c[i];
            Sa += (double)w_d[i]; Sq += (double)w_e[i];
            rmc += w_i[i]; rzce += w_j[i];
        }

        const double Td   = (double)TLEN;
        const double invT = 1.0 / Td;
        double S1 = s_S1;
        double pk = s_pk, pkn = s_pkn;
        int    zct = s_zc + rzce;

        double m         = (double)s_mean;
        // exact reconstruction: Sum x^2 = D2 + 2*m*(S1 - T*m) + T*m^2
        double S2        = D2 + 2.0 * m * (S1 - Td * m) + Td * m * m;

        double meanv     = S1 * invT;
        double var       = D2 / (Td - 1.0);
        double stdv      = sqrt(var);
        double sq_mean   = S2 * invT;
        double rms       = sqrt(sq_mean);
        double ptp       = pk - pkn;
        double abs_peak  = fabs(pk);
        double crest     = abs_peak / (rms + EPSV);
        double mean_abs  = Sa * invT;
        double shape     = rms / (mean_abs + EPSV);
        double impulse   = abs_peak / (mean_abs + EPSV);
        double sqrt_mean = Sq * invT;
        double clearance = abs_peak / (sqrt_mean * sqrt_mean + EPSV);
        double skew      = (D3 * invT) / (stdv * stdv * stdv + EPSV);
        double kurt      = (D4 * invT) / (var * var + EPSV) - 3.0;
        double zcr       = (double)zct / (Td - 1.0);
        double mcr       = (double)rmc / (Td - 1.0);
        double margin    = abs_peak / (sqrt_mean + EPSV);
        double energy    = S2;

        float* o = out + (size_t)row * 17;
        o[0]  = (float)meanv;
        o[1]  = (float)stdv;
        o[2]  = (float)var;
        o[3]  = (float)rms;
        o[4]  = (float)pk;
        o[5]  = (float)pkn;
        o[6]  = (float)ptp;
        o[7]  = (float)crest;
        o[8]  = (float)shape;
        o[9]  = (float)impulse;
        o[10] = (float)clearance;
        o[11] = (float)skew;
        o[12] = (float)kurt;
        o[13] = (float)zcr;
        o[14] = (float)mcr;
        o[15] = (float)margin;
        o[16] = (float)energy;
    }
}

extern "C" void kernel_launch(void* const* d_in, const int* in_sizes, int n_in,
                              void* d_out, int out_size) {
    const float* x = (const float*)d_in[0];
    float* out = (float*)d_out;
    int rows = in_sizes[0] / TLEN;   // 64*16 = 1024
    stat_feat_kernel<<<rows, THREADS>>>(x, out);
}